// round 1
// baseline (speedup 1.0000x reference)
#include <cuda_runtime.h>
#include <math.h>

#define Bc 2
#define Tc 2048
#define Dc 1024
#define Hc 16
#define DH 64
#define Mtot (Bc*Tc)   // 4096

// Scratch (allocation-free): q,k,v in (B,H,T,dh), attn out in (B,T,D)
__device__ float g_q [Bc*Hc*Tc*DH];
__device__ float g_k [Bc*Hc*Tc*DH];
__device__ float g_v [Bc*Hc*Tc*DH];
__device__ float g_ao[Bc*Tc*Dc];

// C = A @ W^T.  A: M x K row-major, W: N x K row-major. M=4096, N=K=1024.
// OUTSEL: 0->g_q, 1->g_k, 2->g_v, 3->Cext (row-major)
// ASEL:   0->Aext, 1->g_ao
// PERM=1: write C[m,n] to (B,H,T,dh) layout (n = h*dh+d, m = b*T+t)
template<int OUTSEL, int ASEL, int PERM>
__global__ __launch_bounds__(256) void gemm_nt_kernel(const float* __restrict__ Aext,
                                                      const float* __restrict__ W,
                                                      float* __restrict__ Cext) {
    const int K = Dc, N = Dc;
    const float* A = (ASEL == 1) ? g_ao : Aext;
    float* C = (OUTSEL == 0) ? g_q : (OUTSEL == 1) ? g_k : (OUTSEL == 2) ? g_v : Cext;

    __shared__ float As[8][128];
    __shared__ float Ws[8][128];

    const int tid  = threadIdx.x;
    const int row0 = blockIdx.y * 128;
    const int col0 = blockIdx.x * 128;
    const int tx = tid % 16;        // 0..15 -> 8 output cols each
    const int ty = tid / 16;        // 0..15 -> 8 output rows each

    const int lr = tid >> 1;        // 0..127 tile row to load
    const int lk = (tid & 1) * 4;   // 0 or 4 within BK=8

    float acc[8][8];
    #pragma unroll
    for (int i = 0; i < 8; i++)
        #pragma unroll
        for (int j = 0; j < 8; j++) acc[i][j] = 0.f;

    const float* Ap = A + (size_t)(row0 + lr) * K + lk;
    const float* Wp = W + (size_t)(col0 + lr) * K + lk;

    for (int k0 = 0; k0 < K; k0 += 8) {
        float4 a = *(const float4*)(Ap + k0);
        float4 w = *(const float4*)(Wp + k0);
        As[lk+0][lr] = a.x; As[lk+1][lr] = a.y; As[lk+2][lr] = a.z; As[lk+3][lr] = a.w;
        Ws[lk+0][lr] = w.x; Ws[lk+1][lr] = w.y; Ws[lk+2][lr] = w.z; Ws[lk+3][lr] = w.w;
        __syncthreads();

        #pragma unroll
        for (int kk = 0; kk < 8; kk++) {
            float4 a0 = *(const float4*)&As[kk][ty*8];
            float4 a1 = *(const float4*)&As[kk][ty*8+4];
            float4 w0 = *(const float4*)&Ws[kk][tx*8];
            float4 w1 = *(const float4*)&Ws[kk][tx*8+4];
            float ar[8] = {a0.x,a0.y,a0.z,a0.w,a1.x,a1.y,a1.z,a1.w};
            float wr[8] = {w0.x,w0.y,w0.z,w0.w,w1.x,w1.y,w1.z,w1.w};
            #pragma unroll
            for (int i = 0; i < 8; i++)
                #pragma unroll
                for (int j = 0; j < 8; j++)
                    acc[i][j] = fmaf(ar[i], wr[j], acc[i][j]);
        }
        __syncthreads();
    }

    #pragma unroll
    for (int i = 0; i < 8; i++) {
        const int m = row0 + ty*8 + i;
        #pragma unroll
        for (int j = 0; j < 8; j++) {
            const int n = col0 + tx*8 + j;
            if (PERM) {
                const int b = m / Tc, t = m % Tc;
                const int h = n / DH, d = n % DH;
                C[(((size_t)(b*Hc + h))*Tc + t)*DH + d] = acc[i][j];
            } else {
                C[(size_t)m * N + n] = acc[i][j];
            }
        }
    }
}

// One thread per query token, online softmax over the sliding window.
__global__ __launch_bounds__(64) void attn_kernel() {
    const int b = blockIdx.z;
    const int h = blockIdx.y;
    const int t = blockIdx.x * 64 + threadIdx.x;

    const size_t head_off = ((size_t)(b*Hc + h)) * Tc * DH;
    const float* qp = g_q + head_off + (size_t)t * DH;
    const float* kb = g_k + head_off;
    const float* vb = g_v + head_off;

    float qr[DH];
    #pragma unroll
    for (int d = 0; d < DH; d++) qr[d] = qp[d];

    float mval = -1e30f, l = 0.f;
    float acc[DH];
    #pragma unroll
    for (int d = 0; d < DH; d++) acc[d] = 0.f;

    int j0 = t - 128; if (j0 < 0) j0 = 0;

    for (int j = j0; j <= t; j++) {
        const float4* kp = (const float4*)(kb + (size_t)j * DH);
        float s = 0.f;
        #pragma unroll
        for (int d4 = 0; d4 < 16; d4++) {
            float4 kv4 = kp[d4];
            s = fmaf(qr[4*d4+0], kv4.x, s);
            s = fmaf(qr[4*d4+1], kv4.y, s);
            s = fmaf(qr[4*d4+2], kv4.z, s);
            s = fmaf(qr[4*d4+3], kv4.w, s);
        }
        s *= 0.125f;  // 1/sqrt(64)

        float mn   = fmaxf(mval, s);
        float corr = __expf(mval - mn);
        float p    = __expf(s - mn);
        l = l * corr + p;

        const float4* vp = (const float4*)(vb + (size_t)j * DH);
        #pragma unroll
        for (int d4 = 0; d4 < 16; d4++) {
            float4 vv = vp[d4];
            acc[4*d4+0] = fmaf(acc[4*d4+0], corr, p * vv.x);
            acc[4*d4+1] = fmaf(acc[4*d4+1], corr, p * vv.y);
            acc[4*d4+2] = fmaf(acc[4*d4+2], corr, p * vv.z);
            acc[4*d4+3] = fmaf(acc[4*d4+3], corr, p * vv.w);
        }
        mval = mn;
    }

    const float inv = 1.f / l;
    float* op = g_ao + ((size_t)b * Tc + t) * Dc + h * DH;
    #pragma unroll
    for (int d = 0; d < DH; d++) op[d] = acc[d] * inv;
}

extern "C" void kernel_launch(void* const* d_in, const int* in_sizes, int n_in,
                              void* d_out, int out_size) {
    const float* x  = (const float*)d_in[0];
    const float* Wq = (const float*)d_in[1];
    const float* Wk = (const float*)d_in[2];
    const float* Wv = (const float*)d_in[3];
    const float* Wo = (const float*)d_in[4];
    float* out = (float*)d_out;

    dim3 gg(Dc/128, Mtot/128);   // (8, 32)
    gemm_nt_kernel<0,0,1><<<gg, 256>>>(x, Wq, nullptr);
    gemm_nt_kernel<1,0,1><<<gg, 256>>>(x, Wk, nullptr);
    gemm_nt_kernel<2,0,1><<<gg, 256>>>(x, Wv, nullptr);

    attn_kernel<<<dim3(Tc/64, Hc, Bc), 64>>>();

    gemm_nt_kernel<3,1,0><<<gg, 256>>>(nullptr, Wo, out);
}

// round 3
// speedup vs baseline: 1.5253x; 1.5253x over previous
#include <cuda_runtime.h>
#include <cstdint>
#include <math.h>

#define Bc 2
#define Tc 2048
#define Dc 1024
#define Hc 16
#define DH 64
#define Mtot (Bc*Tc)   // 4096

// Scratch (allocation-free)
__device__ float g_q [Bc*Hc*Tc*DH];
__device__ float g_k [Bc*Hc*Tc*DH];
__device__ float g_v [Bc*Hc*Tc*DH];
__device__ float g_ao[Bc*Tc*Dc];

// ---------------- helpers ----------------
__device__ __forceinline__ uint32_t smem_u32(const void* p) {
    uint32_t a;
    asm("{ .reg .u64 t; cvta.to.shared.u64 t, %1; cvt.u32.u64 %0, t; }" : "=r"(a) : "l"(p));
    return a;
}
__device__ __forceinline__ void cpa16(uint32_t s, const float* gp) {
    uint64_t g;
    asm("cvta.to.global.u64 %0, %1;" : "=l"(g) : "l"(gp));
    asm volatile("cp.async.cg.shared.global [%0], [%1], 16;" :: "r"(s), "l"(g) : "memory");
}
__device__ __forceinline__ uint32_t tf32cvt(float f) {
    uint32_t u;
    asm("cvt.rna.tf32.f32 %0, %1;" : "=r"(u) : "f"(f));
    return u;
}
__device__ __forceinline__ void mma8(float* c, const uint32_t* a, const uint32_t* b) {
    asm volatile(
        "mma.sync.aligned.m16n8k8.row.col.f32.tf32.tf32.f32 "
        "{%0,%1,%2,%3}, {%4,%5,%6,%7}, {%8,%9}, {%0,%1,%2,%3};"
        : "+f"(c[0]), "+f"(c[1]), "+f"(c[2]), "+f"(c[3])
        : "r"(a[0]), "r"(a[1]), "r"(a[2]), "r"(a[3]), "r"(b[0]), "r"(b[1]));
}

// swizzled float index within a 128x32 tile: row r, col c
__device__ __forceinline__ int swidx(int r, int c) {
    return r * 32 + ((((c >> 2) ^ (r & 7)) << 2) | (c & 3));
}

// ---------------- tf32 mma.sync GEMM: C = A @ W^T ----------------
// A: M x 1024 row-major, W: 1024 x 1024 row-major. Tile 128x128x32.
// 8 warps as 2(m) x 4(n); warp tile 64x32; frags m16n8k8.
// OUTSEL: 0->g_q, 1->g_k, 2->g_v, 3->Cext.  ASEL: 0->Aext, 1->g_ao.
#define SMEM_BYTES 65536   // 2 bufs * (A 16KB + B 16KB)

template<int OUTSEL, int ASEL, int PERM>
__global__ __launch_bounds__(256, 2) void gemm_mma(const float* __restrict__ Aext,
                                                   const float* __restrict__ W,
                                                   float* __restrict__ Cext) {
    extern __shared__ float sm[];     // A: sm[0..8191] (2 bufs), B: sm[8192..16383]
    const float* A = (ASEL == 1) ? g_ao : Aext;
    float* C = (OUTSEL == 0) ? g_q : (OUTSEL == 1) ? g_k : (OUTSEL == 2) ? g_v : Cext;

    const int tid = threadIdx.x;
    const int wid = tid >> 5, lane = tid & 31;
    const int row0 = blockIdx.y * 128;
    const int col0 = blockIdx.x * 128;
    const int wm = (wid & 1) * 64;        // warp m offset
    const int wn = (wid >> 1) * 32;       // warp n offset
    const int g = lane >> 2, tig = lane & 3;

    const uint32_t sbase = smem_u32(sm);
    const int lr = tid >> 3;              // loader row (0..31)
    const int lc4 = tid & 7;              // loader 16B chunk (0..7)

    const float* Ag = A + (size_t)row0 * Dc;
    const float* Bg = W + (size_t)col0 * Dc;

    float acc[4][4][4];
    #pragma unroll
    for (int i = 0; i < 4; i++)
        #pragma unroll
        for (int j = 0; j < 4; j++)
            #pragma unroll
            for (int k = 0; k < 4; k++) acc[i][j][k] = 0.f;

    // issue async loads for K-tile kt into buffer kt&1
    auto issue_tile = [&](int kt) {
        const int buf = kt & 1;
        #pragma unroll
        for (int p = 0; p < 4; p++) {
            const int r = lr + 32 * p;
            const uint32_t so = (uint32_t)(r * 128 + ((lc4 ^ (r & 7)) << 4));
            const size_t go = (size_t)r * Dc + kt * 32 + lc4 * 4;
            cpa16(sbase + buf * 16384 + so, Ag + go);
            cpa16(sbase + 32768 + buf * 16384 + so, Bg + go);
        }
        asm volatile("cp.async.commit_group;" ::: "memory");
    };

    issue_tile(0);

    for (int kt = 0; kt < 32; kt++) {
        if (kt + 1 < 32) {
            issue_tile(kt + 1);
            asm volatile("cp.async.wait_group 1;" ::: "memory");
        } else {
            asm volatile("cp.async.wait_group 0;" ::: "memory");
        }
        __syncthreads();

        const float* Ab = sm + (kt & 1) * 4096;
        const float* Bb = sm + 8192 + (kt & 1) * 4096;

        #pragma unroll
        for (int ks = 0; ks < 4; ks++) {
            const int k0 = ks * 8;
            uint32_t af[4][4], bf[4][2];
            #pragma unroll
            for (int mi = 0; mi < 4; mi++) {
                const int r = wm + mi * 16 + g;
                af[mi][0] = tf32cvt(Ab[swidx(r,     k0 + tig)]);
                af[mi][1] = tf32cvt(Ab[swidx(r + 8, k0 + tig)]);
                af[mi][2] = tf32cvt(Ab[swidx(r,     k0 + 4 + tig)]);
                af[mi][3] = tf32cvt(Ab[swidx(r + 8, k0 + 4 + tig)]);
            }
            #pragma unroll
            for (int ni = 0; ni < 4; ni++) {
                const int rn = wn + ni * 8 + g;
                bf[ni][0] = tf32cvt(Bb[swidx(rn, k0 + tig)]);
                bf[ni][1] = tf32cvt(Bb[swidx(rn, k0 + 4 + tig)]);
            }
            #pragma unroll
            for (int mi = 0; mi < 4; mi++)
                #pragma unroll
                for (int ni = 0; ni < 4; ni++)
                    mma8(acc[mi][ni], af[mi], bf[ni]);
        }
        __syncthreads();
    }

    // epilogue: C frag layout m16n8: c0/c1 at (g, 2*tig[+1]), c2/c3 at (g+8, ...)
    #pragma unroll
    for (int mi = 0; mi < 4; mi++) {
        #pragma unroll
        for (int ni = 0; ni < 4; ni++) {
            const int m0 = row0 + wm + mi * 16 + g;
            const int n  = col0 + wn + ni * 8 + tig * 2;
            float2 v01 = make_float2(acc[mi][ni][0], acc[mi][ni][1]);
            float2 v23 = make_float2(acc[mi][ni][2], acc[mi][ni][3]);
            if (PERM) {
                const int b0i = m0 >> 11, t0 = m0 & 2047;
                const int h = n / DH, d0 = n % DH;
                float* p0 = C + ((((size_t)(b0i * Hc + h)) * Tc + t0) * DH + d0);
                *(float2*)p0 = v01;
                const int m1 = m0 + 8;
                const int b1i = m1 >> 11, t1 = m1 & 2047;
                float* p1 = C + ((((size_t)(b1i * Hc + h)) * Tc + t1) * DH + d0);
                *(float2*)p1 = v23;
            } else {
                *(float2*)(C + (size_t)m0 * Dc + n) = v01;
                *(float2*)(C + (size_t)(m0 + 8) * Dc + n) = v23;
            }
        }
    }
}

// ---------------- attention (unchanged) ----------------
__global__ __launch_bounds__(64) void attn_kernel() {
    const int b = blockIdx.z;
    const int h = blockIdx.y;
    const int t = blockIdx.x * 64 + threadIdx.x;

    const size_t head_off = ((size_t)(b * Hc + h)) * Tc * DH;
    const float* qp = g_q + head_off + (size_t)t * DH;
    const float* kb = g_k + head_off;
    const float* vb = g_v + head_off;

    float qr[DH];
    #pragma unroll
    for (int d = 0; d < DH; d++) qr[d] = qp[d];

    float mval = -1e30f, l = 0.f;
    float acc[DH];
    #pragma unroll
    for (int d = 0; d < DH; d++) acc[d] = 0.f;

    int j0 = t - 128; if (j0 < 0) j0 = 0;

    for (int j = j0; j <= t; j++) {
        const float4* kp = (const float4*)(kb + (size_t)j * DH);
        float s = 0.f;
        #pragma unroll
        for (int d4 = 0; d4 < 16; d4++) {
            float4 kv4 = kp[d4];
            s = fmaf(qr[4 * d4 + 0], kv4.x, s);
            s = fmaf(qr[4 * d4 + 1], kv4.y, s);
            s = fmaf(qr[4 * d4 + 2], kv4.z, s);
            s = fmaf(qr[4 * d4 + 3], kv4.w, s);
        }
        s *= 0.125f;

        float mn   = fmaxf(mval, s);
        float corr = __expf(mval - mn);
        float p    = __expf(s - mn);
        l = l * corr + p;

        const float4* vp = (const float4*)(vb + (size_t)j * DH);
        #pragma unroll
        for (int d4 = 0; d4 < 16; d4++) {
            float4 vv = vp[d4];
            acc[4 * d4 + 0] = fmaf(acc[4 * d4 + 0], corr, p * vv.x);
            acc[4 * d4 + 1] = fmaf(acc[4 * d4 + 1], corr, p * vv.y);
            acc[4 * d4 + 2] = fmaf(acc[4 * d4 + 2], corr, p * vv.z);
            acc[4 * d4 + 3] = fmaf(acc[4 * d4 + 3], corr, p * vv.w);
        }
        mval = mn;
    }

    const float inv = 1.f / l;
    float* op = g_ao + ((size_t)b * Tc + t) * Dc + h * DH;
    #pragma unroll
    for (int d = 0; d < DH; d++) op[d] = acc[d] * inv;
}

extern "C" void kernel_launch(void* const* d_in, const int* in_sizes, int n_in,
                              void* d_out, int out_size) {
    const float* x  = (const float*)d_in[0];
    const float* Wq = (const float*)d_in[1];
    const float* Wk = (const float*)d_in[2];
    const float* Wv = (const float*)d_in[3];
    const float* Wo = (const float*)d_in[4];
    float* out = (float*)d_out;

    cudaFuncSetAttribute(gemm_mma<0,0,1>, cudaFuncAttributeMaxDynamicSharedMemorySize, SMEM_BYTES);
    cudaFuncSetAttribute(gemm_mma<1,0,1>, cudaFuncAttributeMaxDynamicSharedMemorySize, SMEM_BYTES);
    cudaFuncSetAttribute(gemm_mma<2,0,1>, cudaFuncAttributeMaxDynamicSharedMemorySize, SMEM_BYTES);
    cudaFuncSetAttribute(gemm_mma<3,1,0>, cudaFuncAttributeMaxDynamicSharedMemorySize, SMEM_BYTES);

    dim3 gg(Dc / 128, Mtot / 128);   // (8, 32) = 256 CTAs
    gemm_mma<0,0,1><<<gg, 256, SMEM_BYTES>>>(x, Wq, nullptr);
    gemm_mma<1,0,1><<<gg, 256, SMEM_BYTES>>>(x, Wk, nullptr);
    gemm_mma<2,0,1><<<gg, 256, SMEM_BYTES>>>(x, Wv, nullptr);

    attn_kernel<<<dim3(Tc / 64, Hc, Bc), 64>>>();

    gemm_mma<3,1,0><<<gg, 256, SMEM_BYTES>>>(nullptr, Wo, out);
}